// round 2
// baseline (speedup 1.0000x reference)
#include <cuda_runtime.h>
#include <cuda_bf16.h>
#include <math.h>

#define L     8
#define NH    16
#define DH    64
#define SMAX  2048
#define H     1024
#define FFN   4096
#define ENC   1500
#define VOCAB 8192
#define FCH   94   // enc f-chunk for k_wsum (16*94 >= 1500)

// ---------------- device state ----------------
__device__ float g_x[H];
__device__ float g_qkv[3 * H];      // q | k1 | v1
__device__ float g_ao[H];           // self-attn output
__device__ float g_qc[H];           // cross query
__device__ float g_U[H * NH];       // U[i][h] = sum_d Ck[i,h*64+d]*qc[h,d]
__device__ float g_sc[NH * ENC];    // cross scores -> attc (in place)
__device__ float g_W[NH * H];       // W[h][i] = sum_f attc[h,f]*enc[f,i]
__device__ float g_outc[H];         // cross-attn output
__device__ float g_ffn[FFN];
__device__ float g_logits[VOCAB];
__device__ float g_pm[NH * 8];      // flash-decode partial max
__device__ float g_ps[NH * 8];      // partial sum
__device__ float g_po[NH * 8 * DH]; // partial weighted V
__device__ int   g_step_fallback[1] = {512};

// ---------------- block reductions (blockDim multiple of 32, <=1024) ----------------
__device__ __forceinline__ float br_sum(float v, float* sb) {
    int tid = threadIdx.x, lane = tid & 31, w = tid >> 5;
#pragma unroll
    for (int o = 16; o; o >>= 1) v += __shfl_down_sync(0xffffffffu, v, o);
    if (lane == 0) sb[w] = v;
    __syncthreads();
    if (tid < 32) {
        int nw = (blockDim.x + 31) >> 5;
        float x = (tid < nw) ? sb[tid] : 0.0f;
#pragma unroll
        for (int o = 16; o; o >>= 1) x += __shfl_down_sync(0xffffffffu, x, o);
        if (tid == 0) sb[0] = x;
    }
    __syncthreads();
    float r = sb[0];
    __syncthreads();
    return r;
}

__device__ __forceinline__ float br_max(float v, float* sb) {
    int tid = threadIdx.x, lane = tid & 31, w = tid >> 5;
#pragma unroll
    for (int o = 16; o; o >>= 1) v = fmaxf(v, __shfl_down_sync(0xffffffffu, v, o));
    if (lane == 0) sb[w] = v;
    __syncthreads();
    if (tid < 32) {
        int nw = (blockDim.x + 31) >> 5;
        float x = (tid < nw) ? sb[tid] : -1e30f;
#pragma unroll
        for (int o = 16; o; o >>= 1) x = fmaxf(x, __shfl_down_sync(0xffffffffu, x, o));
        if (tid == 0) sb[0] = x;
    }
    __syncthreads();
    float r = sb[0];
    __syncthreads();
    return r;
}

// LN stats of g_x computed redundantly per block
__device__ __forceinline__ void ln_stats(float* sb, float& mean, float& rstd) {
    int tid = threadIdx.x;
    float s = 0.f;
    for (int i = tid; i < H; i += blockDim.x) s += g_x[i];
    mean = br_sum(s, sb) * (1.0f / H);
    float v = 0.f;
    for (int i = tid; i < H; i += blockDim.x) { float d = g_x[i] - mean; v += d * d; }
    rstd = rsqrtf(br_sum(v, sb) * (1.0f / H) + 1e-5f);
}

// ---------------- kernels ----------------

// big cache copy: nk/nv = cache[:step] ++ (slot written later) ++ zeros
__global__ void k_copy(const float4* __restrict__ ck, const float4* __restrict__ cv,
                       float4* __restrict__ nk, float4* __restrict__ nv,
                       const int* __restrict__ stepp) {
    int step = stepp[0];
    size_t idx = (size_t)blockIdx.x * blockDim.x + threadIdx.x;
    const size_t half = (size_t)L * NH * SMAX * 16;  // float4 units per tensor
    if (idx >= 2 * half) return;
    const float4* src; float4* dst; size_t pos;
    if (idx < half) { src = ck; dst = nk; pos = idx; }
    else            { src = cv; dst = nv; pos = idx - half; }
    int t = (int)((pos >> 4) & (SMAX - 1));
    if (t < step)      dst[pos] = src[pos];
    else if (t > step) dst[pos] = make_float4(0.f, 0.f, 0.f, 0.f);
}

// x = tok_emb[id] + pos_emb[step]; zero qkv
__global__ void k_init(const int* __restrict__ idp, const int* __restrict__ stepp,
                       const float* __restrict__ tok, const float* __restrict__ pos) {
    int tid = threadIdx.x;  // 1024
    int id = idp[0], st = stepp[0];
    g_x[tid] = tok[(size_t)id * H + tid] + pos[(size_t)st * H + tid];
    for (int i = tid; i < 3 * H; i += 1024) g_qkv[i] = 0.f;
}

// qkv += LN1(x) @ [Wq|Wk|Wv], split-K (grid: 12 x 32, block 256)
__global__ void k_gemv3_ln(const float* __restrict__ Wq, const float* __restrict__ Wk,
                           const float* __restrict__ Wv,
                           const float* __restrict__ g, const float* __restrict__ b) {
    __shared__ float sb[32];
    __shared__ float hc[32];
    int tid = threadIdx.x;
    float mean, rstd;
    ln_stats(sb, mean, rstd);
    int i0 = blockIdx.y * 32;
    if (tid < 32) { int i = i0 + tid; hc[tid] = (g_x[i] - mean) * rstd * g[i] + b[i]; }
    __syncthreads();
    int j = blockIdx.x * 256 + tid;  // 0..3071
    const float* Wm = (j < H) ? Wq : ((j < 2 * H) ? Wk : Wv);
    int jj = j & (H - 1);
    float acc = 0.f;
#pragma unroll
    for (int r = 0; r < 32; r++) acc += hc[r] * Wm[(size_t)(i0 + r) * H + jj];
    atomicAdd(&g_qkv[j], acc);
}

// out += LN(x; g,b) @ W  (grid: n_out/256 x 32, block 256)
__global__ void k_gemv_ln(const float* __restrict__ Wm,
                          const float* __restrict__ g, const float* __restrict__ b,
                          float* __restrict__ out, int n_out) {
    __shared__ float sb[32];
    __shared__ float hc[32];
    int tid = threadIdx.x;
    float mean, rstd;
    ln_stats(sb, mean, rstd);
    int i0 = blockIdx.y * 32;
    if (tid < 32) { int i = i0 + tid; hc[tid] = (g_x[i] - mean) * rstd * g[i] + b[i]; }
    __syncthreads();
    int j = blockIdx.x * 256 + tid;
    float acc = 0.f;
#pragma unroll
    for (int r = 0; r < 32; r++) acc += hc[r] * Wm[(size_t)(i0 + r) * n_out + j];
    atomicAdd(&out[j], acc);
}

// out += (relu?)a @ W  (grid: n_out/256 x n_in/32, block 256); optional zeroing of 2 buffers
__global__ void k_gemv_plain(const float* __restrict__ Wm, const float* __restrict__ a,
                             float* __restrict__ out, int n_out, int relu,
                             float* z1, int zn1, float* z2, int zn2) {
    __shared__ float ac[32];
    int tid = threadIdx.x;
    int gt = (blockIdx.y * gridDim.x + blockIdx.x) * blockDim.x + tid;
    int T = gridDim.x * gridDim.y * blockDim.x;
    for (int k = gt; k < zn1; k += T) z1[k] = 0.f;
    for (int k = gt; k < zn2; k += T) z2[k] = 0.f;
    int i0 = blockIdx.y * 32;
    if (tid < 32) { float x = a[i0 + tid]; if (relu) x = fmaxf(x, 0.f); ac[tid] = x; }
    __syncthreads();
    int j = blockIdx.x * 256 + tid;
    float acc = 0.f;
#pragma unroll
    for (int r = 0; r < 32; r++) acc += ac[r] * Wm[(size_t)(i0 + r) * n_out + j];
    atomicAdd(&out[j], acc);
}

// flash-decode partials: grid (16 heads, 8 chunks), block 256
__global__ void k_attn_part(const float* __restrict__ ck, const float* __restrict__ cv,
                            const int* __restrict__ stepp, int l) {
    __shared__ float q_s[64];
    __shared__ float sc[264];
    __shared__ float sb[32];
    __shared__ float red[256];
    int tid = threadIdx.x;
    int h = blockIdx.x, c = blockIdx.y;
    int step = stepp[0];
    int n = step + 1;
    int cs = (n + 7) / 8;
    int k0 = c * cs;
    int k1 = min(n, k0 + cs);
    int cnt = k1 - k0;
    if (tid < 64) q_s[tid] = g_qkv[h * 64 + tid];
    __syncthreads();
    int w = tid >> 5, lane = tid & 31;
    const float* kbase = ck + (size_t)(l * NH + h) * SMAX * DH;
    for (int kk = k0 + w; kk < k1; kk += 8) {
        const float* kp = (kk < step) ? (kbase + (size_t)kk * DH) : (&g_qkv[H + h * 64]);
        float v = kp[lane] * q_s[lane] + kp[lane + 32] * q_s[lane + 32];
#pragma unroll
        for (int o = 16; o; o >>= 1) v += __shfl_down_sync(0xffffffffu, v, o);
        if (lane == 0) sc[kk - k0] = v * 0.125f;
    }
    __syncthreads();
    float m = -1e30f;
    for (int i = tid; i < cnt; i += 256) m = fmaxf(m, sc[i]);
    m = br_max(m, sb);
    float s = 0.f;
    for (int i = tid; i < cnt; i += 256) { float e = expf(sc[i] - m); sc[i] = e; s += e; }
    s = br_sum(s, sb);
    int d = tid & 63, part = tid >> 6;
    const float* vbase = cv + (size_t)(l * NH + h) * SMAX * DH;
    float acc = 0.f;
    for (int kk = k0 + part; kk < k1; kk += 4) {
        const float* vp = (kk < step) ? (vbase + (size_t)kk * DH) : (&g_qkv[2 * H + h * 64]);
        acc += sc[kk - k0] * vp[d];
    }
    red[tid] = acc;
    __syncthreads();
    if (part == 0) {
        float o = red[d] + red[64 + d] + red[128 + d] + red[192 + d];
        g_po[(h * 8 + c) * 64 + d] = o;
        if (d == 0) { g_pm[h * 8 + c] = m; g_ps[h * 8 + c] = s; }
    }
}

// merge partials -> ao; write k1/v1 into output caches; zero g_qc. grid 16, block 128
__global__ void k_attn_merge(float* __restrict__ nk, float* __restrict__ nv,
                             const int* __restrict__ stepp, int l) {
    int h = blockIdx.x, tid = threadIdx.x;
    int step = stepp[0];
    float M = -1e30f;
#pragma unroll
    for (int c = 0; c < 8; c++) M = fmaxf(M, g_pm[h * 8 + c]);
    float S = 0.f;
#pragma unroll
    for (int c = 0; c < 8; c++) S += g_ps[h * 8 + c] * expf(g_pm[h * 8 + c] - M);
    if (tid < 64) {
        float o = 0.f;
#pragma unroll
        for (int c = 0; c < 8; c++) o += expf(g_pm[h * 8 + c] - M) * g_po[(h * 8 + c) * 64 + tid];
        g_ao[h * 64 + tid] = o / S;
        g_qc[h * 64 + tid] = 0.f;
    } else {
        int d = tid - 64;
        size_t slot = ((size_t)(l * NH + h) * SMAX + step) * DH + d;
        nk[slot] = g_qkv[H + h * 64 + d];
        nv[slot] = g_qkv[2 * H + h * 64 + d];
    }
}

// U[i][h] = sum_d Ck[i, h*64+d] * qc[h*64+d]; warp per (i,h). grid 2048, block 256
__global__ void k_U(const float* __restrict__ Ck) {
    int wid = (blockIdx.x * blockDim.x + threadIdx.x) >> 5;
    int lane = threadIdx.x & 31;
    if (wid >= H * NH) return;
    int h = wid & (NH - 1);
    int i = wid >> 4;
    const float* cp = Ck + (size_t)i * H + h * 64;
    float v = cp[lane] * g_qc[h * 64 + lane] + cp[lane + 32] * g_qc[h * 64 + 32 + lane];
#pragma unroll
    for (int o = 16; o; o >>= 1) v += __shfl_down_sync(0xffffffffu, v, o);
    if (lane == 0) g_U[i * NH + h] = v;
}

// scores[h][f] = scale * enc[f] . U[:,h] + cmask[f]. grid 1500, block 256
__global__ void k_scores(const float* __restrict__ enc, const float* __restrict__ cmask) {
    __shared__ float sb[32];
    int f = blockIdx.x, tid = threadIdx.x;
    float acc[NH];
#pragma unroll
    for (int h = 0; h < NH; h++) acc[h] = 0.f;
    for (int i = tid; i < H; i += 256) {
        float e = enc[(size_t)f * H + i];
        const float* u = &g_U[i * NH];
#pragma unroll
        for (int h = 0; h < NH; h++) acc[h] += e * u[h];
    }
    float cm = cmask[f];
#pragma unroll
    for (int h = 0; h < NH; h++) {
        float s = br_sum(acc[h], sb);
        if (tid == 0) g_sc[h * ENC + f] = s * 0.125f + cm;
    }
}

// per-head softmax over ENC; zero g_W and g_outc. grid 16, block 256
__global__ void k_softmax16() {
    __shared__ float sb[32];
    int h = blockIdx.x, tid = threadIdx.x;
    float* row = &g_sc[h * ENC];
    float m = -1e30f;
    for (int i = tid; i < ENC; i += 256) m = fmaxf(m, row[i]);
    m = br_max(m, sb);
    float s = 0.f;
    for (int i = tid; i < ENC; i += 256) { float e = expf(row[i] - m); row[i] = e; s += e; }
    s = br_sum(s, sb);
    float inv = 1.f / s;
    for (int i = tid; i < ENC; i += 256) row[i] *= inv;
    for (int i = tid; i < H; i += 256) g_W[h * H + i] = 0.f;
    if (h == 0) for (int i = tid; i < H; i += 256) g_outc[i] = 0.f;
}

// W[h][col] += sum_f attc[h,f]*enc[f,col]. grid (4 col-tiles, 16 f-chunks), block 256
__global__ void k_wsum(const float* __restrict__ enc) {
    __shared__ float at[NH * FCH];
    int tid = threadIdx.x, fc = blockIdx.y;
    for (int idx = tid; idx < NH * FCH; idx += 256) {
        int h = idx / FCH, k = idx % FCH;
        int f = fc * FCH + k;
        at[idx] = (f < ENC) ? g_sc[h * ENC + f] : 0.f;
    }
    __syncthreads();
    int col = blockIdx.x * 256 + tid;
    float acc[NH];
#pragma unroll
    for (int h = 0; h < NH; h++) acc[h] = 0.f;
    int fend = min(FCH, ENC - fc * FCH);
    for (int k = 0; k < fend; k++) {
        float e = enc[(size_t)(fc * FCH + k) * H + col];
#pragma unroll
        for (int h = 0; h < NH; h++) acc[h] += at[h * FCH + k] * e;
    }
#pragma unroll
    for (int h = 0; h < NH; h++) atomicAdd(&g_W[h * H + col], acc[h]);
}

// outc[h*64+d] += sum_i W[h,i]*Cv[i, h*64+d]; zero g_ffn. grid (16 heads, 16 i-chunks), block 64
__global__ void k_outc(const float* __restrict__ Cv) {
    int tid = threadIdx.x;
    int h = blockIdx.x, i0 = blockIdx.y * 64;
    float acc = 0.f;
#pragma unroll 8
    for (int r = 0; r < 64; r++) {
        int i = i0 + r;
        acc += g_W[h * H + i] * Cv[(size_t)i * H + h * 64 + tid];
    }
    atomicAdd(&g_outc[h * 64 + tid], acc);
    int gt = (blockIdx.y * gridDim.x + blockIdx.x) * 64 + tid;  // 0..16383
    if (gt < FFN) g_ffn[gt] = 0.f;
}

// final log_softmax over VOCAB. grid 1, block 256
__global__ void k_logsoftmax(float* __restrict__ out) {
    __shared__ float sb[32];
    int tid = threadIdx.x;
    float m = -1e30f;
    for (int i = tid; i < VOCAB; i += 256) m = fmaxf(m, g_logits[i]);
    m = br_max(m, sb);
    float s = 0.f;
    for (int i = tid; i < VOCAB; i += 256) s += expf(g_logits[i] - m);
    s = br_sum(s, sb);
    float ls = logf(s);
    for (int i = tid; i < VOCAB; i += 256) out[i] = g_logits[i] - m - ls;
}

// ---------------- host ----------------
extern "C" void kernel_launch(void* const* d_in, const int* in_sizes, int n_in,
                              void* d_out, int out_size) {
    int has_step = (n_in >= 27) ? 1 : 0;
    int idx = 0;
    const int*   input_id = (const int*)d_in[idx++];
    const float* enc      = (const float*)d_in[idx++];
    const float* ck       = (const float*)d_in[idx++];
    const float* cv       = (const float*)d_in[idx++];
    const int*   stepp    = nullptr;
    if (has_step) stepp = (const int*)d_in[idx++];
    const float* cmask = (const float*)d_in[idx++];
    const float* tok   = (const float*)d_in[idx++];
    const float* pos   = (const float*)d_in[idx++];
    const float* Wq = (const float*)d_in[idx++];
    const float* Wk = (const float*)d_in[idx++];
    const float* Wv = (const float*)d_in[idx++];
    const float* Wo = (const float*)d_in[idx++];
    const float* Cq = (const float*)d_in[idx++];
    const float* Ck = (const float*)d_in[idx++];
    const float* Cv = (const float*)d_in[idx++];
    const float* Co = (const float*)d_in[idx++];
    const float* W1 = (const float*)d_in[idx++];
    const float* W2 = (const float*)d_in[idx++];
    const float* ln1g = (const float*)d_in[idx++];
    const float* ln1b = (const float*)d_in[idx++];
    const float* ln2g = (const float*)d_in[idx++];
    const float* ln2b = (const float*)d_in[idx++];
    const float* ln3g = (const float*)d_in[idx++];
    const float* ln3b = (const float*)d_in[idx++];
    const float* lnfg = (const float*)d_in[idx++];
    const float* lnfb = (const float*)d_in[idx++];
    const float* Wout = (const float*)d_in[idx++];

    if (!stepp) {
        void* p;
        cudaGetSymbolAddress(&p, g_step_fallback);
        stepp = (const int*)p;
    }

    float* out = (float*)d_out;
    float* nk = out + VOCAB;
    float* nv = nk + (size_t)L * NH * SMAX * DH;

    // symbol addresses for generic kernels
    float *p_x, *p_ao, *p_qc, *p_outc, *p_ffn, *p_logits, *p_qkv;
    cudaGetSymbolAddress((void**)&p_x, g_x);
    cudaGetSymbolAddress((void**)&p_ao, g_ao);
    cudaGetSymbolAddress((void**)&p_qc, g_qc);
    cudaGetSymbolAddress((void**)&p_outc, g_outc);
    cudaGetSymbolAddress((void**)&p_ffn, g_ffn);
    cudaGetSymbolAddress((void**)&p_logits, g_logits);
    cudaGetSymbolAddress((void**)&p_qkv, g_qkv);

    // independent big cache copy
    k_copy<<<32768, 256>>>((const float4*)ck, (const float4*)cv,
                           (float4*)nk, (float4*)nv, stepp);
    // embedding + zero qkv
    k_init<<<1, 1024>>>(input_id, stepp, tok, pos);

    for (int l = 0; l < L; l++) {
        size_t o = (size_t)l * H * H;
        size_t o1 = (size_t)l * H * FFN;
        size_t o2 = (size_t)l * FFN * H;
        // self-attention
        k_gemv3_ln<<<dim3(12, 32), 256>>>(Wq + o, Wk + o, Wv + o, ln1g + l * H, ln1b + l * H);
        k_attn_part<<<dim3(16, 8), 256>>>(ck, cv, stepp, l);
        k_attn_merge<<<16, 128>>>(nk, nv, stepp, l);
        k_gemv_plain<<<dim3(4, 32), 256>>>(Wo + o, p_ao, p_x, H, 0, nullptr, 0, nullptr, 0);
        // cross-attention (algebraically refactored: no enc@Ck / enc@Cv rebuild)
        k_gemv_ln<<<dim3(4, 32), 256>>>(Cq + o, ln2g + l * H, ln2b + l * H, p_qc, H);
        k_U<<<2048, 256>>>(Ck + o);
        k_scores<<<ENC, 256>>>(enc, cmask);
        k_softmax16<<<16, 256>>>();
        k_wsum<<<dim3(4, 16), 256>>>(enc);
        k_outc<<<dim3(16, 16), 64>>>(Cv + o);
        k_gemv_plain<<<dim3(4, 32), 256>>>(Co + o, p_outc, p_x, H, 0, nullptr, 0, nullptr, 0);
        // FFN
        k_gemv_ln<<<dim3(16, 32), 256>>>(W1 + o1, ln3g + l * H, ln3b + l * H, p_ffn, FFN);
        k_gemv_plain<<<dim3(4, 128), 256>>>(W2 + o2, p_ffn, p_x, H, 1,
                                            p_qkv, 3 * H, p_logits, VOCAB);
    }
    // final projection + log-softmax
    k_gemv_ln<<<dim3(32, 32), 256>>>(Wout, lnfg, lnfb, p_logits, VOCAB);
    k_logsoftmax<<<1, 256>>>(out);
}

// round 3
// speedup vs baseline: 1.6358x; 1.6358x over previous
#include <cuda_runtime.h>
#include <cuda_bf16.h>
#include <math.h>

#define L     8
#define NH    16
#define DH    64
#define SMAX  2048
#define H     1024
#define FFN   4096
#define ENC   1500
#define VOCAB 8192
#define FCH   48   // enc f-chunk for k_wsum (32*48 >= 1500)

// ---------------- device state ----------------
__device__ __align__(16) float g_x[H];
__device__ __align__(16) float g_qkv[3 * H];      // q | k1 | v1
__device__ __align__(16) float g_ao[H];           // self-attn output
__device__ __align__(16) float g_qc[H];           // cross query
__device__ __align__(16) float g_U[NH * H];       // U[h][i] = sum_d Ck[i,h*64+d]*qc[h,d]  (TRANSPOSED)
__device__ float g_sc[NH * ENC];    // cross scores -> attc (in place)
__device__ __align__(16) float g_W[NH * H];       // W[h][i] = sum_f attc[h,f]*enc[f,i]
__device__ __align__(16) float g_outc[H];         // cross-attn output
__device__ float g_ffn[FFN];
__device__ float g_logits[VOCAB];
__device__ float g_pm[NH * 8];      // flash-decode partial max
__device__ float g_ps[NH * 8];      // partial sum
__device__ float g_po[NH * 8 * DH]; // partial weighted V
__device__ int   g_step_fallback[1] = {512};

// ---------------- block reductions (blockDim multiple of 32, <=1024) ----------------
__device__ __forceinline__ float br_sum(float v, float* sb) {
    int tid = threadIdx.x, lane = tid & 31, w = tid >> 5;
#pragma unroll
    for (int o = 16; o; o >>= 1) v += __shfl_down_sync(0xffffffffu, v, o);
    if (lane == 0) sb[w] = v;
    __syncthreads();
    if (tid < 32) {
        int nw = (blockDim.x + 31) >> 5;
        float x = (tid < nw) ? sb[tid] : 0.0f;
#pragma unroll
        for (int o = 16; o; o >>= 1) x += __shfl_down_sync(0xffffffffu, x, o);
        if (tid == 0) sb[0] = x;
    }
    __syncthreads();
    float r = sb[0];
    __syncthreads();
    return r;
}

__device__ __forceinline__ float br_max(float v, float* sb) {
    int tid = threadIdx.x, lane = tid & 31, w = tid >> 5;
#pragma unroll
    for (int o = 16; o; o >>= 1) v = fmaxf(v, __shfl_down_sync(0xffffffffu, v, o));
    if (lane == 0) sb[w] = v;
    __syncthreads();
    if (tid < 32) {
        int nw = (blockDim.x + 31) >> 5;
        float x = (tid < nw) ? sb[tid] : -1e30f;
#pragma unroll
        for (int o = 16; o; o >>= 1) x = fmaxf(x, __shfl_down_sync(0xffffffffu, x, o));
        if (tid == 0) sb[0] = x;
    }
    __syncthreads();
    float r = sb[0];
    __syncthreads();
    return r;
}

// LN stats of g_x computed redundantly per block
__device__ __forceinline__ void ln_stats(float* sb, float& mean, float& rstd) {
    int tid = threadIdx.x;
    float s = 0.f;
    for (int i = tid; i < H; i += blockDim.x) s += g_x[i];
    mean = br_sum(s, sb) * (1.0f / H);
    float v = 0.f;
    for (int i = tid; i < H; i += blockDim.x) { float d = g_x[i] - mean; v += d * d; }
    rstd = rsqrtf(br_sum(v, sb) * (1.0f / H) + 1e-5f);
}

// ---------------- kernels ----------------

// big cache copy: nk/nv = cache[:step] ++ (slot written later) ++ zeros
__global__ void k_copy(const float4* __restrict__ ck, const float4* __restrict__ cv,
                       float4* __restrict__ nk, float4* __restrict__ nv,
                       const int* __restrict__ stepp) {
    int step = stepp[0];
    size_t idx = (size_t)blockIdx.x * blockDim.x + threadIdx.x;
    const size_t half = (size_t)L * NH * SMAX * 16;  // float4 units per tensor
    if (idx >= 2 * half) return;
    const float4* src; float4* dst; size_t pos;
    if (idx < half) { src = ck; dst = nk; pos = idx; }
    else            { src = cv; dst = nv; pos = idx - half; }
    int t = (int)((pos >> 4) & (SMAX - 1));
    if (t < step)      dst[pos] = src[pos];
    else if (t > step) dst[pos] = make_float4(0.f, 0.f, 0.f, 0.f);
}

// x = tok_emb[id] + pos_emb[step]; zero qkv
__global__ void k_init(const int* __restrict__ idp, const int* __restrict__ stepp,
                       const float* __restrict__ tok, const float* __restrict__ pos) {
    int tid = threadIdx.x;  // 1024
    int id = idp[0], st = stepp[0];
    g_x[tid] = tok[(size_t)id * H + tid] + pos[(size_t)st * H + tid];
    for (int i = tid; i < 3 * H; i += 1024) g_qkv[i] = 0.f;
}

// qkv += LN1(x) @ [Wq|Wk|Wv], split-K 16 rows (grid: 12 x 64, block 256)
__global__ void k_gemv3_ln(const float* __restrict__ Wq, const float* __restrict__ Wk,
                           const float* __restrict__ Wv,
                           const float* __restrict__ g, const float* __restrict__ b) {
    __shared__ float sb[32];
    __shared__ float hc[16];
    int tid = threadIdx.x;
    float mean, rstd;
    ln_stats(sb, mean, rstd);
    int i0 = blockIdx.y * 16;
    if (tid < 16) { int i = i0 + tid; hc[tid] = (g_x[i] - mean) * rstd * g[i] + b[i]; }
    __syncthreads();
    int j = blockIdx.x * 256 + tid;  // 0..3071
    const float* Wm = (j < H) ? Wq : ((j < 2 * H) ? Wk : Wv);
    int jj = j & (H - 1);
    float acc = 0.f;
#pragma unroll
    for (int r = 0; r < 16; r++) acc += hc[r] * Wm[(size_t)(i0 + r) * H + jj];
    atomicAdd(&g_qkv[j], acc);
}

// out += LN(x; g,b) @ W  (grid: n_out/256 x 64, block 256)
__global__ void k_gemv_ln(const float* __restrict__ Wm,
                          const float* __restrict__ g, const float* __restrict__ b,
                          float* __restrict__ out, int n_out) {
    __shared__ float sb[32];
    __shared__ float hc[16];
    int tid = threadIdx.x;
    float mean, rstd;
    ln_stats(sb, mean, rstd);
    int i0 = blockIdx.y * 16;
    if (tid < 16) { int i = i0 + tid; hc[tid] = (g_x[i] - mean) * rstd * g[i] + b[i]; }
    __syncthreads();
    int j = blockIdx.x * 256 + tid;
    float acc = 0.f;
#pragma unroll
    for (int r = 0; r < 16; r++) acc += hc[r] * Wm[(size_t)(i0 + r) * n_out + j];
    atomicAdd(&out[j], acc);
}

// out += (relu?)a @ W  (grid: n_out/256 x n_in/16, block 256); optional zeroing of 2 buffers
__global__ void k_gemv_plain(const float* __restrict__ Wm, const float* __restrict__ a,
                             float* __restrict__ out, int n_out, int relu,
                             float* z1, int zn1, float* z2, int zn2) {
    __shared__ float ac[16];
    int tid = threadIdx.x;
    int gt = (blockIdx.y * gridDim.x + blockIdx.x) * blockDim.x + tid;
    int T = gridDim.x * gridDim.y * blockDim.x;
    for (int k = gt; k < zn1; k += T) z1[k] = 0.f;
    for (int k = gt; k < zn2; k += T) z2[k] = 0.f;
    int i0 = blockIdx.y * 16;
    if (tid < 16) { float x = a[i0 + tid]; if (relu) x = fmaxf(x, 0.f); ac[tid] = x; }
    __syncthreads();
    int j = blockIdx.x * 256 + tid;
    float acc = 0.f;
#pragma unroll
    for (int r = 0; r < 16; r++) acc += ac[r] * Wm[(size_t)(i0 + r) * n_out + j];
    atomicAdd(&out[j], acc);
}

// flash-decode partials: grid (16 heads, 8 chunks), block 256
// thread-per-key scoring (float4 loads, no shuffle chains) + coalesced V pass
__global__ void k_attn_part(const float* __restrict__ ck, const float* __restrict__ cv,
                            const int* __restrict__ stepp, int l) {
    __shared__ float q_s[64];
    __shared__ float sc[264];
    __shared__ float sb[32];
    __shared__ float red[256];
    int tid = threadIdx.x;
    int h = blockIdx.x, c = blockIdx.y;
    int step = stepp[0];
    int n = step + 1;
    int cs = (n + 7) >> 3;
    int k0 = c * cs;
    int k1 = min(n, k0 + cs);
    int cnt = k1 - k0;  // can be <= 0 for tiny n; handled below
    if (tid < 64) q_s[tid] = g_qkv[h * 64 + tid];
    __syncthreads();
    const float* kbase = ck + (size_t)(l * NH + h) * SMAX * DH;
    for (int t = tid; t < cnt; t += 256) {
        int kk = k0 + t;
        const float4* kp = (kk < step) ? (const float4*)(kbase + (size_t)kk * DH)
                                       : (const float4*)(&g_qkv[H + h * 64]);
        float acc = 0.f;
#pragma unroll
        for (int j = 0; j < 16; j++) {
            float4 kv = kp[j];
            acc += kv.x * q_s[4*j] + kv.y * q_s[4*j+1] + kv.z * q_s[4*j+2] + kv.w * q_s[4*j+3];
        }
        sc[t] = acc * 0.125f;
    }
    __syncthreads();
    float m = -1e30f;
    for (int i = tid; i < cnt; i += 256) m = fmaxf(m, sc[i]);
    m = br_max(m, sb);
    float s = 0.f;
    for (int i = tid; i < cnt; i += 256) { float e = expf(sc[i] - m); sc[i] = e; s += e; }
    s = br_sum(s, sb);
    int d = tid & 63, part = tid >> 6;
    const float* vbase = cv + (size_t)(l * NH + h) * SMAX * DH;
    float acc = 0.f;
    for (int kk = k0 + part; kk < k1; kk += 4) {
        const float* vp = (kk < step) ? (vbase + (size_t)kk * DH) : (&g_qkv[2 * H + h * 64]);
        acc += sc[kk - k0] * vp[d];
    }
    red[tid] = acc;
    __syncthreads();
    if (part == 0) {
        float o = red[d] + red[64 + d] + red[128 + d] + red[192 + d];
        g_po[(h * 8 + c) * 64 + d] = o;
        if (d == 0) { g_pm[h * 8 + c] = m; g_ps[h * 8 + c] = s; }
    }
}

// merge partials -> ao; write k1/v1 into output caches; zero g_qc. grid 16, block 128
__global__ void k_attn_merge(float* __restrict__ nk, float* __restrict__ nv,
                             const int* __restrict__ stepp, int l) {
    int h = blockIdx.x, tid = threadIdx.x;
    int step = stepp[0];
    float M = -1e30f;
#pragma unroll
    for (int c = 0; c < 8; c++) M = fmaxf(M, g_pm[h * 8 + c]);
    float S = 0.f;
#pragma unroll
    for (int c = 0; c < 8; c++) S += g_ps[h * 8 + c] * expf(g_pm[h * 8 + c] - M);
    if (tid < 64) {
        float o = 0.f;
#pragma unroll
        for (int c = 0; c < 8; c++) o += expf(g_pm[h * 8 + c] - M) * g_po[(h * 8 + c) * 64 + tid];
        g_ao[h * 64 + tid] = o / S;
        g_qc[h * 64 + tid] = 0.f;
    } else {
        int d = tid - 64;
        size_t slot = ((size_t)(l * NH + h) * SMAX + step) * DH + d;
        nk[slot] = g_qkv[H + h * 64 + d];
        nv[slot] = g_qkv[2 * H + h * 64 + d];
    }
}

// U[h][i] = sum_d Ck[i, h*64+d] * qc[h*64+d]; warp per (i,h). grid 2048, block 256
__global__ void k_U(const float* __restrict__ Ck) {
    int wid = (blockIdx.x * blockDim.x + threadIdx.x) >> 5;
    int lane = threadIdx.x & 31;
    if (wid >= H * NH) return;
    int h = wid & (NH - 1);
    int i = wid >> 4;
    const float2* cp = (const float2*)(Ck + (size_t)i * H + h * 64);
    const float2* qp = (const float2*)(&g_qc[h * 64]);
    float2 cvv = cp[lane], qv = qp[lane];
    float v = cvv.x * qv.x + cvv.y * qv.y;
#pragma unroll
    for (int o = 16; o; o >>= 1) v += __shfl_down_sync(0xffffffffu, v, o);
    if (lane == 0) g_U[h * H + i] = v;  // transposed layout
}

// scores[h][f] = scale * enc[f] . U[h] + cmask[f].
// grid ceil(ENC/8)=188, block 512 (warp w = head w), U row register-resident.
__global__ void k_scores(const float* __restrict__ enc, const float* __restrict__ cmask) {
    int w = threadIdx.x >> 5, lane = threadIdx.x & 31;
    const float4* up = (const float4*)(g_U + w * H);
    float4 u[8];
#pragma unroll
    for (int j = 0; j < 8; j++) u[j] = up[lane + 32 * j];
#pragma unroll
    for (int ff = 0; ff < 8; ff++) {
        int f = blockIdx.x * 8 + ff;
        if (f >= ENC) break;
        const float4* ep = (const float4*)(enc + (size_t)f * H);
        float acc = 0.f;
#pragma unroll
        for (int j = 0; j < 8; j++) {
            float4 e = ep[lane + 32 * j];
            acc += e.x * u[j].x + e.y * u[j].y + e.z * u[j].z + e.w * u[j].w;
        }
#pragma unroll
        for (int o = 16; o; o >>= 1) acc += __shfl_down_sync(0xffffffffu, acc, o);
        if (lane == 0) g_sc[w * ENC + f] = acc * 0.125f + cmask[f];
    }
}

// per-head softmax over ENC; zero g_W and g_outc. grid 16, block 256
__global__ void k_softmax16() {
    __shared__ float sb[32];
    int h = blockIdx.x, tid = threadIdx.x;
    float* row = &g_sc[h * ENC];
    float m = -1e30f;
    for (int i = tid; i < ENC; i += 256) m = fmaxf(m, row[i]);
    m = br_max(m, sb);
    float s = 0.f;
    for (int i = tid; i < ENC; i += 256) { float e = expf(row[i] - m); row[i] = e; s += e; }
    s = br_sum(s, sb);
    float inv = 1.f / s;
    for (int i = tid; i < ENC; i += 256) row[i] *= inv;
    for (int i = tid; i < H; i += 256) g_W[h * H + i] = 0.f;
    if (h == 0) for (int i = tid; i < H; i += 256) g_outc[i] = 0.f;
}

// W[h][col] += sum_f attc[h,f]*enc[f,col]. grid (4 col-tiles, 32 f-chunks), block 256
__global__ void k_wsum(const float* __restrict__ enc) {
    __shared__ float at[NH * FCH];
    int tid = threadIdx.x, fc = blockIdx.y;
    for (int idx = tid; idx < NH * FCH; idx += 256) {
        int h = idx / FCH, k = idx % FCH;
        int f = fc * FCH + k;
        at[idx] = (f < ENC) ? g_sc[h * ENC + f] : 0.f;
    }
    __syncthreads();
    int col = blockIdx.x * 256 + tid;
    float acc[NH];
#pragma unroll
    for (int h = 0; h < NH; h++) acc[h] = 0.f;
    int fend = min(FCH, ENC - fc * FCH);
    for (int k = 0; k < fend; k++) {
        float e = enc[(size_t)(fc * FCH + k) * H + col];
#pragma unroll
        for (int h = 0; h < NH; h++) acc[h] += at[h * FCH + k] * e;
    }
#pragma unroll
    for (int h = 0; h < NH; h++) atomicAdd(&g_W[h * H + col], acc[h]);
}

// outc[col] += sum_i W[h(col),i]*Cv[i,col]; zero g_ffn. grid (4 col-tiles, 16 i-chunks), block 256
__global__ void k_outc(const float* __restrict__ Cv) {
    int tid = threadIdx.x;
    int col = blockIdx.x * 256 + tid;
    int h = col >> 6;
    int i0 = blockIdx.y * 64;
    float acc = 0.f;
#pragma unroll 8
    for (int r = 0; r < 64; r++) {
        int i = i0 + r;
        acc += g_W[h * H + i] * Cv[(size_t)i * H + col];
    }
    atomicAdd(&g_outc[col], acc);
    int gt = (blockIdx.y * gridDim.x + blockIdx.x) * 256 + tid;  // 0..16383
    if (gt < FFN) g_ffn[gt] = 0.f;
}

// final log_softmax over VOCAB. grid 1, block 256
__global__ void k_logsoftmax(float* __restrict__ out) {
    __shared__ float sb[32];
    int tid = threadIdx.x;
    float m = -1e30f;
    for (int i = tid; i < VOCAB; i += 256) m = fmaxf(m, g_logits[i]);
    m = br_max(m, sb);
    float s = 0.f;
    for (int i = tid; i < VOCAB; i += 256) s += expf(g_logits[i] - m);
    s = br_sum(s, sb);
    float ls = logf(s);
    for (int i = tid; i < VOCAB; i += 256) out[i] = g_logits[i] - m - ls;
}

// ---------------- host ----------------
extern "C" void kernel_launch(void* const* d_in, const int* in_sizes, int n_in,
                              void* d_out, int out_size) {
    int has_step = (n_in >= 27) ? 1 : 0;
    int idx = 0;
    const int*   input_id = (const int*)d_in[idx++];
    const float* enc      = (const float*)d_in[idx++];
    const float* ck       = (const float*)d_in[idx++];
    const float* cv       = (const float*)d_in[idx++];
    const int*   stepp    = nullptr;
    if (has_step) stepp = (const int*)d_in[idx++];
    const float* cmask = (const float*)d_in[idx++];
    const float* tok   = (const float*)d_in[idx++];
    const float* pos   = (const float*)d_in[idx++];
    const float* Wq = (const float*)d_in[idx++];
    const float* Wk = (const float*)d_in[idx++];
    const float* Wv = (const float*)d_in[idx++];
    const float* Wo = (const float*)d_in[idx++];
    const float* Cq = (const float*)d_in[idx++];
    const float* Ck = (const float*)d_in[idx++];
    const float* Cv = (const float*)d_in[idx++];
    const float* Co = (const float*)d_in[idx++];
    const float* W1 = (const float*)d_in[idx++];
    const float* W2 = (const float*)d_in[idx++];
    const float* ln1g = (const float*)d_in[idx++];
    const float* ln1b = (const float*)d_in[idx++];
    const float* ln2g = (const float*)d_in[idx++];
    const float* ln2b = (const float*)d_in[idx++];
    const float* ln3g = (const float*)d_in[idx++];
    const float* ln3b = (const float*)d_in[idx++];
    const float* lnfg = (const float*)d_in[idx++];
    const float* lnfb = (const float*)d_in[idx++];
    const float* Wout = (const float*)d_in[idx++];

    if (!stepp) {
        void* p;
        cudaGetSymbolAddress(&p, g_step_fallback);
        stepp = (const int*)p;
    }

    float* out = (float*)d_out;
    float* nk = out + VOCAB;
    float* nv = nk + (size_t)L * NH * SMAX * DH;

    // symbol addresses for generic kernels
    float *p_x, *p_ao, *p_qc, *p_outc, *p_ffn, *p_logits, *p_qkv;
    cudaGetSymbolAddress((void**)&p_x, g_x);
    cudaGetSymbolAddress((void**)&p_ao, g_ao);
    cudaGetSymbolAddress((void**)&p_qc, g_qc);
    cudaGetSymbolAddress((void**)&p_outc, g_outc);
    cudaGetSymbolAddress((void**)&p_ffn, g_ffn);
    cudaGetSymbolAddress((void**)&p_logits, g_logits);
    cudaGetSymbolAddress((void**)&p_qkv, g_qkv);

    // independent big cache copy
    k_copy<<<32768, 256>>>((const float4*)ck, (const float4*)cv,
                           (float4*)nk, (float4*)nv, stepp);
    // embedding + zero qkv
    k_init<<<1, 1024>>>(input_id, stepp, tok, pos);

    for (int l = 0; l < L; l++) {
        size_t o = (size_t)l * H * H;
        size_t o1 = (size_t)l * H * FFN;
        size_t o2 = (size_t)l * FFN * H;
        // self-attention
        k_gemv3_ln<<<dim3(12, 64), 256>>>(Wq + o, Wk + o, Wv + o, ln1g + l * H, ln1b + l * H);
        k_attn_part<<<dim3(16, 8), 256>>>(ck, cv, stepp, l);
        k_attn_merge<<<16, 128>>>(nk, nv, stepp, l);
        k_gemv_plain<<<dim3(4, 64), 256>>>(Wo + o, p_ao, p_x, H, 0, nullptr, 0, nullptr, 0);
        // cross-attention (algebraically refactored: no enc@Ck / enc@Cv rebuild)
        k_gemv_ln<<<dim3(4, 64), 256>>>(Cq + o, ln2g + l * H, ln2b + l * H, p_qc, H);
        k_U<<<2048, 256>>>(Ck + o);
        k_scores<<<188, 512>>>(enc, cmask);
        k_softmax16<<<16, 256>>>();
        k_wsum<<<dim3(4, 32), 256>>>(enc);
        k_outc<<<dim3(4, 16), 256>>>(Cv + o);
        k_gemv_plain<<<dim3(4, 64), 256>>>(Co + o, p_outc, p_x, H, 0, nullptr, 0, nullptr, 0);
        // FFN
        k_gemv_ln<<<dim3(16, 64), 256>>>(W1 + o1, ln3g + l * H, ln3b + l * H, p_ffn, FFN);
        k_gemv_plain<<<dim3(4, 256), 256>>>(W2 + o2, p_ffn, p_x, H, 1,
                                            p_qkv, 3 * H, p_logits, VOCAB);
    }
    // final projection + log-softmax
    k_gemv_ln<<<dim3(32, 64), 256>>>(Wout, lnfg, lnfb, p_logits, VOCAB);
    k_logsoftmax<<<1, 256>>>(out);
}